// round 14
// baseline (speedup 1.0000x reference)
#include <cuda_runtime.h>
#include <math.h>

#define Bn 8
#define An 100000
#define Cn 80
#define TOPN 1000
#define MAXOBJ 100
#define CAP 32768

__device__ unsigned       g_keys[Bn * An];
__device__ unsigned       g_cand[Bn * CAP];
__device__ unsigned       g_ccnt[Bn];        // zero-init; reset inside k_post

#define ARGM(v, base, m, mi) \
    do { \
        if ((v).x > (m)) { (m) = (v).x; (mi) = (base); } \
        if ((v).y > (m)) { (m) = (v).y; (mi) = (base) + 1; } \
        if ((v).z > (m)) { (m) = (v).z; (mi) = (base) + 2; } \
        if ((v).w > (m)) { (m) = (v).w; (mi) = (base) + 3; } \
    } while (0)

// exact: iou >= 0.5  <=>  3*inter >= ai+aj (all quantities integer-valued f32)
__device__ __forceinline__ bool iou_ge(float4 bi, float ai, float4 bj, float aj) {
    float tlx = fmaxf(bi.x, bj.x), tly = fmaxf(bi.y, bj.y);
    float brx = fminf(bi.z, bj.z), bry = fminf(bi.w, bj.w);
    float sx = fmaxf(__fsub_rn(brx, tlx), 0.f);
    float sy = fmaxf(__fsub_rn(bry, tly), 0.f);
    float inter = __fmul_rn(sx, sy);
    return __fmul_rn(3.f, inter) >= __fadd_rn(ai, aj);
}

// ---------- kernel 1: max-only scoring (no argmax), 2 anchors / 8 lanes ----------
__global__ __launch_bounds__(256) void k_score(const float4* __restrict__ cls4) {
    int T = blockIdx.x * 256 + threadIdx.x;
    int g = T >> 3, r = T & 7;
    int a0 = g * 2;
    const float4* p = cls4 + (size_t)g * 40;

    float4 v0 = __ldcs(p + r);
    float4 v1 = __ldcs(p + 8 + r);
    float4 v2 = __ldcs(p + 16 + r);
    float4 v3 = __ldcs(p + 24 + r);
    float4 v4 = __ldcs(p + 32 + r);

    float m0 = fmaxf(fmaxf(v0.x, v0.y), fmaxf(v0.z, v0.w));
    m0 = fmaxf(m0, fmaxf(fmaxf(v1.x, v1.y), fmaxf(v1.z, v1.w)));
    float m1 = fmaxf(fmaxf(v3.x, v3.y), fmaxf(v3.z, v3.w));
    m1 = fmaxf(m1, fmaxf(fmaxf(v4.x, v4.y), fmaxf(v4.z, v4.w)));
    float m2 = fmaxf(fmaxf(v2.x, v2.y), fmaxf(v2.z, v2.w));
    if (r < 4) m0 = fmaxf(m0, m2);
    else       m1 = fmaxf(m1, m2);

    // max-only reduction over the 8-lane group
#pragma unroll
    for (int o = 1; o < 8; o <<= 1) {
        m0 = fmaxf(m0, __shfl_xor_sync(0xffffffffu, m0, o));
        m1 = fmaxf(m1, __shfl_xor_sync(0xffffffffu, m1, o));
    }
    unsigned b0 = __float_as_uint(m0), b1 = __float_as_uint(m1);
    unsigned u0 = (m0 > 0.05f) ? ((b0 < 0x3F800000u) ? (0x3F800000u - b0) : 0u) : 0xFFFFFFFFu;
    unsigned u1 = (m1 > 0.05f) ? ((b1 < 0x3F800000u) ? (0x3F800000u - b1) : 0u) : 0xFFFFFFFFu;

    if (r == 0)
        *reinterpret_cast<uint2*>(&g_keys[a0]) = make_uint2(u0, u1);

    unsigned msk0 = __ballot_sync(0xffffffffu, (r == 0) && u0 < 16380u);
    unsigned msk1 = __ballot_sync(0xffffffffu, (r == 0) && u1 < 16380u);
    unsigned tot = (unsigned)(__popc(msk0) + __popc(msk1));
    if (tot) {
        int b = a0 / An;
        int leader = __ffs(msk0 | msk1) - 1;
        unsigned base = 0;
        if ((threadIdx.x & 31) == leader) base = atomicAdd(&g_ccnt[b], tot);
        base = __shfl_sync(0xffffffffu, base, leader);
        if (r == 0) {
            unsigned lanebit = 1u << (threadIdx.x & 31);
            int al = a0 - b * An;
            if (u0 < 16380u) {
                unsigned p2 = base + (unsigned)__popc(msk0 & (lanebit - 1u));
                if (p2 < CAP) g_cand[b * CAP + p2] = (u0 << 17) | (unsigned)al;
            }
            if (u1 < 16380u) {
                unsigned p2 = base + (unsigned)__popc(msk0)
                            + (unsigned)__popc(msk1 & (lanebit - 1u));
                if (p2 < CAP) g_cand[b * CAP + p2] = (u1 << 17) | (unsigned)(al + 1);
            }
        }
    }
}

// ---------- kernel 2: select + sort + decode + class-argmax (top-1000 only) + greedy ----------
__global__ __launch_bounds__(1024) void k_post(const float4* __restrict__ cls4,
                                               const float4* __restrict__ reg,
                                               const float4* __restrict__ anc,
                                               float* __restrict__ out) {
    __shared__ __align__(16) unsigned hist[4096];   // aliased: sk32 / sk64
    __shared__ float4 sbox[1024];
    __shared__ float  sarea[1024];
    __shared__ int    sanchor[1024];
    __shared__ int    sclass[1024];
    __shared__ unsigned wsum[32];
    __shared__ int s_cut;
    __shared__ unsigned s_tot, s_n;
    __shared__ unsigned s_keptw[32], s_invalid[32], s_cross[32];
    __shared__ int s_kcnt;
    __shared__ int s_base[32];

    int b = blockIdx.x, tid = threadIdx.x;
    int lane = tid & 31, wid = tid >> 5;

    unsigned ccnt = g_ccnt[b];
    unsigned cc = (ccnt < (unsigned)CAP) ? ccnt : (unsigned)CAP;
    const unsigned* cand = g_cand + b * CAP;

    if (tid < MAXOBJ) {
        out[b * MAXOBJ + tid] = -1.f;
        out[Bn * MAXOBJ + b * MAXOBJ + tid] = -1.f;
    }
    if (tid < MAXOBJ * 4) out[2 * Bn * MAXOBJ + b * MAXOBJ * 4 + tid] = 0.f;

    for (int i = tid; i < 4096; i += 1024) hist[i] = 0u;
    if (tid == 0) { s_cut = -1; s_tot = 0u; s_n = 0u; s_kcnt = 0; }
    if (tid < 32) s_keptw[tid] = 0u;
    __syncthreads();

    for (unsigned c = tid; c < cc; c += 1024)
        atomicAdd(&hist[(cand[c] >> 17) >> 2], 1u);
    __syncthreads();

    unsigned h0 = hist[4 * tid], h1 = hist[4 * tid + 1],
             h2 = hist[4 * tid + 2], h3 = hist[4 * tid + 3];
    unsigned s = h0 + h1 + h2 + h3;
    unsigned x = s;
#pragma unroll
    for (int o = 1; o < 32; o <<= 1) {
        unsigned y = __shfl_up_sync(0xffffffffu, x, o);
        if (lane >= o) x += y;
    }
    if (lane == 31) wsum[wid] = x;
    __syncthreads();
    if (tid < 32) {
        unsigned v = wsum[tid];
#pragma unroll
        for (int o = 1; o < 32; o <<= 1) {
            unsigned y = __shfl_up_sync(0xffffffffu, v, o);
            if (tid >= o) v += y;
        }
        wsum[tid] = v;
    }
    __syncthreads();
    unsigned incl = x + (wid ? wsum[wid - 1] : 0u);
    unsigned excl = incl - s;
    if (excl < TOPN && incl >= TOPN) {
        int cut; unsigned c;
        if (excl + h0 >= TOPN)                { cut = 4 * tid;     c = excl + h0; }
        else if (excl + h0 + h1 >= TOPN)      { cut = 4 * tid + 1; c = excl + h0 + h1; }
        else if (excl + h0 + h1 + h2 >= TOPN) { cut = 4 * tid + 2; c = excl + h0 + h1 + h2; }
        else                                  { cut = 4 * tid + 3; c = excl + h0 + h1 + h2 + h3; }
        s_cut = cut; s_tot = c;
    }
    __syncthreads();

    bool fast = (s_cut >= 0) && (s_tot <= 1024u) && (ccnt <= (unsigned)CAP);
    unsigned* sk32 = hist;
    unsigned long long* sk64 = (unsigned long long*)hist;
    unsigned long long key = ~0ull;

    if (fast) {
        unsigned ulimit = ((unsigned)s_cut + 1u) << 2;
        for (unsigned c = tid; c < cc; c += 1024) {
            unsigned k2 = cand[c];
            bool sel = (k2 >> 17) < ulimit;
            unsigned am = __activemask();
            unsigned bal = __ballot_sync(am, sel);
            if (bal) {
                int leader = __ffs(bal) - 1;
                unsigned base = 0;
                if (lane == leader) base = atomicAdd(&s_n, (unsigned)__popc(bal));
                base = __shfl_sync(am, base, leader);
                if (sel) sk32[base + __popc(bal & ((1u << lane) - 1u))] = k2;
            }
        }
        __syncthreads();
        unsigned n = s_n;
        unsigned v = (tid < (int)n) ? sk32[tid] : 0xFFFFFFFFu;
        __syncthreads();
#pragma unroll
        for (int kk = 2; kk <= 32; kk <<= 1) {
            for (int j = kk >> 1; j > 0; j >>= 1) {
                unsigned o = __shfl_xor_sync(0xffffffffu, v, j);
                bool keepmin = ((tid & kk) == 0) == ((tid & j) == 0);
                v = keepmin ? (v < o ? v : o) : (v > o ? v : o);
            }
        }
        for (int kk = 64; kk <= 1024; kk <<= 1) {
            for (int j = kk >> 1; j >= 32; j >>= 1) {
                sk32[tid] = v;
                __syncthreads();
                unsigned o = sk32[tid ^ j];
                __syncthreads();
                bool keepmin = ((tid & kk) == 0) == ((tid & j) == 0);
                v = keepmin ? (v < o ? v : o) : (v > o ? v : o);
            }
#pragma unroll
            for (int j = 16; j > 0; j >>= 1) {
                unsigned o = __shfl_xor_sync(0xffffffffu, v, j);
                bool keepmin = ((tid & kk) == 0) == ((tid & j) == 0);
                v = keepmin ? (v < o ? v : o) : (v > o ? v : o);
            }
        }
        key = (unsigned long long)v;
    } else {
        const unsigned* keys = g_keys + (size_t)b * An;
        unsigned long long pref = 0ull;
        int rankNeed = TOPN;
        __shared__ unsigned s_c;
        for (int bit = 48; bit >= 0; --bit) {
            if (tid == 0) s_c = 0u;
            __syncthreads();
            unsigned c = 0;
            for (int a = tid; a < An; a += 1024) {
                unsigned long long k = ((unsigned long long)keys[a] << 17) | (unsigned)a;
                if ((k >> (bit + 1)) == pref && !((k >> bit) & 1ull)) c++;
            }
#pragma unroll
            for (int o = 16; o; o >>= 1) c += __shfl_down_sync(0xffffffffu, c, o);
            if (lane == 0) atomicAdd(&s_c, c);
            __syncthreads();
            unsigned C0 = s_c;
            if (rankNeed <= (int)C0) pref <<= 1;
            else { pref = (pref << 1) | 1ull; rankNeed -= (int)C0; }
            __syncthreads();
        }
        for (int a = tid; a < An; a += 1024) {
            unsigned long long k = ((unsigned long long)keys[a] << 17) | (unsigned)a;
            if (k <= pref) {
                unsigned p = atomicAdd(&s_n, 1u);
                if (p < 1024u) sk64[p] = k;
            }
        }
        __syncthreads();
        unsigned n = s_n;
        if ((unsigned)tid >= n) sk64[tid] = ~0ull;
        __syncthreads();
        for (int kk = 2; kk <= 1024; kk <<= 1) {
            for (int j = kk >> 1; j > 0; j >>= 1) {
                int ixj = tid ^ j;
                if (ixj > tid) {
                    unsigned long long a0 = sk64[tid], a1 = sk64[ixj];
                    bool asc = (tid & kk) == 0;
                    if (asc ? (a0 > a1) : (a0 < a1)) { sk64[tid] = a1; sk64[ixj] = a0; }
                }
                __syncthreads();
            }
        }
        key = sk64[tid];
    }

    // gather + decode into registers
    unsigned n_real = s_n;
    float sc = 0.f;
    float4 mybox = make_float4(0.f, 0.f, 0.f, 0.f);
    float myarea = 1e9f;
    if (tid < TOPN && (unsigned)tid < n_real) {
        int a = (int)(key & 0x1FFFFull);
        unsigned u = (unsigned)(key >> 17);
        sc = (u >= 0x3F800000u) ? 0.f : __uint_as_float(0x3F800000u - u);
        sanchor[tid] = a;

        float4 rg = __ldg(reg + (size_t)b * An + a);
        float4 an = __ldg(anc + (size_t)b * An + a);
        float aw  = __fsub_rn(an.z, an.x), ah = __fsub_rn(an.w, an.y);
        float acx = __fadd_rn(an.x, __fmul_rn(0.5f, aw));
        float acy = __fadd_rn(an.y, __fmul_rn(0.5f, ah));
        float pw  = __fmul_rn(expf(rg.z), aw);
        float ph  = __fmul_rn(expf(rg.w), ah);
        float pcx = __fadd_rn(__fmul_rn(rg.x, aw), acx);
        float pcy = __fadd_rn(__fmul_rn(rg.y, ah), acy);
        float hw  = __fmul_rn(0.5f, pw), hh = __fmul_rn(0.5f, ph);
        mybox.x = truncf(__fsub_rn(pcx, hw));
        mybox.y = truncf(__fsub_rn(pcy, hh));
        mybox.z = truncf(__fadd_rn(pcx, hw));
        mybox.w = truncf(__fadd_rn(pcy, hh));
        myarea = fmaxf(__fmul_rn(__fsub_rn(mybox.z, mybox.x), __fsub_rn(mybox.w, mybox.y)), 1e-4f);
        sbox[tid] = mybox;
        sarea[tid] = myarea;
    } else {
        sanchor[tid] = -1;
        sbox[tid] = make_float4(1e9f, 1e9f, 1e9f, 1e9f);
        sarea[tid] = 1e9f;
    }
    bool valid = (tid < TOPN) && (sc > 0.05f);
    unsigned wm = __ballot_sync(0xffffffffu, valid);
    if (lane == 0) s_invalid[wid] = ~wm;
    if (tid == 0) g_ccnt[b] = 0u;             // reset for next graph replay
    __syncthreads();

    // ---- class argmax for the selected 1000 anchors only (8 lanes/box, 8 passes) ----
    const float4* clsb = cls4 + (size_t)b * An * 20;
#pragma unroll
    for (int pass = 0; pass < 8; ++pass) {
        int idx = pass * 128 + (tid >> 3);
        int r = tid & 7;
        int a = sanchor[idx];
        float m = -1.f; int mi = 127;
        if (a >= 0) {
            const float4* pc = clsb + (size_t)a * 20;
#pragma unroll
            for (int k = 0; k < 3; ++k) {
                int f = k * 8 + r;
                if (f < 20) {
                    float4 v = __ldg(pc + f);
                    ARGM(v, 4 * f, m, mi);
                }
            }
        }
#pragma unroll
        for (int o = 1; o < 8; o <<= 1) {
            float om = __shfl_xor_sync(0xffffffffu, m, o);
            int   oi = __shfl_xor_sync(0xffffffffu, mi, o);
            if (om > m || (om == m && oi < mi)) { m = om; mi = oi; }
        }
        if (r == 0) sclass[idx] = mi;
    }
    __syncthreads();
    float clf = (float)sclass[tid];

    // ---- lazy chunked greedy NMS ----
    for (int c = 0; c < 32; ++c) {
        if (s_kcnt >= MAXOBJ) break;
        int cbase = c << 5;
        if (wid < c) {
            unsigned kb = s_keptw[wid];
            float4 bb = sbox[cbase + lane]; float ab = sarea[cbase + lane];
            bool hit = false;
            int wb = wid << 5;
#pragma unroll
            for (int t = 0; t < 32; ++t) {
                if ((kb >> t) & 1u)
                    hit |= iou_ge(sbox[wb + t], sarea[wb + t], bb, ab);
            }
            unsigned cw = __ballot_sync(0xffffffffu, hit);
            if (lane == 0) s_cross[wid] = cw;
        }
        {
            float4 bw = sbox[cbase + wid]; float aw_ = sarea[cbase + wid];
            float4 bj = sbox[cbase + lane]; float aj = sarea[cbase + lane];
            bool hit2 = (lane > wid) && iou_ge(bw, aw_, bj, aj);
            unsigned row = __ballot_sync(0xffffffffu, hit2);
            if (lane == 0) hist[2048 + wid] = row;
        }
        __syncthreads();
        unsigned myrow = hist[2048 + lane];
        unsigned sup32 = s_invalid[c];
        for (int w = 0; w < c; ++w) sup32 |= s_cross[w];
        unsigned kept32 = 0u;
#pragma unroll
        for (int t = 0; t < 32; ++t) {
            unsigned rowt = __shfl_sync(0xffffffffu, myrow, t);
            if (!((sup32 >> t) & 1u)) { kept32 |= (1u << t); sup32 |= rowt; }
        }
        if (tid == 0) { s_keptw[c] = kept32; s_kcnt += __popc(kept32); }
        __syncthreads();
    }

    if (tid < 32) {
        unsigned kw = s_keptw[lane];
        int c = __popc(kw), xx = c;
#pragma unroll
        for (int o = 1; o < 32; o <<= 1) {
            int y = __shfl_up_sync(0xffffffffu, xx, o);
            if (lane >= o) xx += y;
        }
        s_base[lane] = xx - c;
    }
    __syncthreads();

    if (tid < TOPN) {
        unsigned kw = s_keptw[wid];
        if ((kw >> lane) & 1u) {
            int r = s_base[wid] + __popc(kw & ((1u << lane) - 1u));
            if (r < MAXOBJ) {
                out[b * MAXOBJ + r] = sc;
                out[Bn * MAXOBJ + b * MAXOBJ + r] = clf;
                float* ob = out + 2 * Bn * MAXOBJ + (b * MAXOBJ + r) * 4;
                ob[0] = mybox.x; ob[1] = mybox.y; ob[2] = mybox.z; ob[3] = mybox.w;
            }
        }
    }
}

extern "C" void kernel_launch(void* const* d_in, const int* in_sizes, int n_in,
                              void* d_out, int out_size) {
    const float*  cls = (const float*)d_in[0];
    const float4* reg = (const float4*)d_in[1];
    const float4* anc = (const float4*)d_in[2];
    float* out = (float*)d_out;

    k_score<<<(Bn * An / 2 * 8) / 256, 256>>>((const float4*)cls);
    k_post<<<Bn, 1024>>>((const float4*)cls, reg, anc, out);
}

// round 15
// speedup vs baseline: 1.1047x; 1.1047x over previous
#include <cuda_runtime.h>
#include <math.h>

#define Bn 8
#define An 100000
#define Cn 80
#define TOPN 1000
#define MAXOBJ 100
#define CAP 32768

__device__ unsigned       g_keys[Bn * An];
__device__ unsigned       g_cand[Bn * CAP];
__device__ unsigned       g_ccnt[Bn];        // zero-init; reset inside k_post

#define ARGM(v, base, m, mi) \
    do { \
        if ((v).x > (m)) { (m) = (v).x; (mi) = (base); } \
        if ((v).y > (m)) { (m) = (v).y; (mi) = (base) + 1; } \
        if ((v).z > (m)) { (m) = (v).z; (mi) = (base) + 2; } \
        if ((v).w > (m)) { (m) = (v).w; (mi) = (base) + 3; } \
    } while (0)

// exact: iou >= 0.5  <=>  3*inter >= ai+aj (all quantities integer-valued f32)
__device__ __forceinline__ bool iou_ge(float4 bi, float ai, float4 bj, float aj) {
    float tlx = fmaxf(bi.x, bj.x), tly = fmaxf(bi.y, bj.y);
    float brx = fminf(bi.z, bj.z), bry = fminf(bi.w, bj.w);
    float sx = fmaxf(__fsub_rn(brx, tlx), 0.f);
    float sy = fmaxf(__fsub_rn(bry, tly), 0.f);
    float inter = __fmul_rn(sx, sy);
    return __fmul_rn(3.f, inter) >= __fadd_rn(ai, aj);
}

// ---------- kernel 1: max-only scoring (no argmax), 2 anchors / 8 lanes ----------
__global__ __launch_bounds__(256) void k_score(const float4* __restrict__ cls4) {
    int T = blockIdx.x * 256 + threadIdx.x;
    int g = T >> 3, r = T & 7;
    int a0 = g * 2;
    const float4* p = cls4 + (size_t)g * 40;

    float4 v0 = __ldcs(p + r);
    float4 v1 = __ldcs(p + 8 + r);
    float4 v2 = __ldcs(p + 16 + r);
    float4 v3 = __ldcs(p + 24 + r);
    float4 v4 = __ldcs(p + 32 + r);

    float m0 = fmaxf(fmaxf(v0.x, v0.y), fmaxf(v0.z, v0.w));
    m0 = fmaxf(m0, fmaxf(fmaxf(v1.x, v1.y), fmaxf(v1.z, v1.w)));
    float m1 = fmaxf(fmaxf(v3.x, v3.y), fmaxf(v3.z, v3.w));
    m1 = fmaxf(m1, fmaxf(fmaxf(v4.x, v4.y), fmaxf(v4.z, v4.w)));
    float m2 = fmaxf(fmaxf(v2.x, v2.y), fmaxf(v2.z, v2.w));
    if (r < 4) m0 = fmaxf(m0, m2);
    else       m1 = fmaxf(m1, m2);

#pragma unroll
    for (int o = 1; o < 8; o <<= 1) {
        m0 = fmaxf(m0, __shfl_xor_sync(0xffffffffu, m0, o));
        m1 = fmaxf(m1, __shfl_xor_sync(0xffffffffu, m1, o));
    }
    unsigned b0 = __float_as_uint(m0), b1 = __float_as_uint(m1);
    unsigned u0 = (m0 > 0.05f) ? ((b0 < 0x3F800000u) ? (0x3F800000u - b0) : 0u) : 0xFFFFFFFFu;
    unsigned u1 = (m1 > 0.05f) ? ((b1 < 0x3F800000u) ? (0x3F800000u - b1) : 0u) : 0xFFFFFFFFu;

    if (r == 0)
        *reinterpret_cast<uint2*>(&g_keys[a0]) = make_uint2(u0, u1);

    unsigned msk0 = __ballot_sync(0xffffffffu, (r == 0) && u0 < 16380u);
    unsigned msk1 = __ballot_sync(0xffffffffu, (r == 0) && u1 < 16380u);
    unsigned tot = (unsigned)(__popc(msk0) + __popc(msk1));
    if (tot) {
        int b = a0 / An;
        int leader = __ffs(msk0 | msk1) - 1;
        unsigned base = 0;
        if ((threadIdx.x & 31) == leader) base = atomicAdd(&g_ccnt[b], tot);
        base = __shfl_sync(0xffffffffu, base, leader);
        if (r == 0) {
            unsigned lanebit = 1u << (threadIdx.x & 31);
            int al = a0 - b * An;
            if (u0 < 16380u) {
                unsigned p2 = base + (unsigned)__popc(msk0 & (lanebit - 1u));
                if (p2 < CAP) g_cand[b * CAP + p2] = (u0 << 17) | (unsigned)al;
            }
            if (u1 < 16380u) {
                unsigned p2 = base + (unsigned)__popc(msk0)
                            + (unsigned)__popc(msk1 & (lanebit - 1u));
                if (p2 < CAP) g_cand[b * CAP + p2] = (u1 << 17) | (unsigned)(al + 1);
            }
        }
    }
}

// ---------- kernel 2: select + sort + decode + greedy + kept-only class argmax ----------
__global__ __launch_bounds__(1024) void k_post(const float4* __restrict__ cls4,
                                               const float4* __restrict__ reg,
                                               const float4* __restrict__ anc,
                                               float* __restrict__ out) {
    __shared__ __align__(16) unsigned hist[4096];   // aliased: sk32 / sk64 / rowmask scratch
    __shared__ float4 sbox[1024];
    __shared__ float  sarea[1024];
    __shared__ int    sanchor[1024];
    __shared__ int    s_list[MAXOBJ];
    __shared__ unsigned wsum[32];
    __shared__ int s_cut;
    __shared__ unsigned s_tot, s_n;
    __shared__ unsigned s_keptw[32], s_invalid[32], s_cross[32];
    __shared__ int s_kcnt;
    __shared__ int s_base[32];

    int b = blockIdx.x, tid = threadIdx.x;
    int lane = tid & 31, wid = tid >> 5;

    unsigned ccnt = g_ccnt[b];
    unsigned cc = (ccnt < (unsigned)CAP) ? ccnt : (unsigned)CAP;
    const unsigned* cand = g_cand + b * CAP;

    if (tid < MAXOBJ) {
        out[b * MAXOBJ + tid] = -1.f;
        out[Bn * MAXOBJ + b * MAXOBJ + tid] = -1.f;
    }
    if (tid < MAXOBJ * 4) out[2 * Bn * MAXOBJ + b * MAXOBJ * 4 + tid] = 0.f;

    for (int i = tid; i < 4096; i += 1024) hist[i] = 0u;
    if (tid == 0) { s_cut = -1; s_tot = 0u; s_n = 0u; s_kcnt = 0; }
    if (tid < 32) s_keptw[tid] = 0u;
    __syncthreads();

    for (unsigned c = tid; c < cc; c += 1024)
        atomicAdd(&hist[(cand[c] >> 17) >> 2], 1u);
    __syncthreads();

    unsigned h0 = hist[4 * tid], h1 = hist[4 * tid + 1],
             h2 = hist[4 * tid + 2], h3 = hist[4 * tid + 3];
    unsigned s = h0 + h1 + h2 + h3;
    unsigned x = s;
#pragma unroll
    for (int o = 1; o < 32; o <<= 1) {
        unsigned y = __shfl_up_sync(0xffffffffu, x, o);
        if (lane >= o) x += y;
    }
    if (lane == 31) wsum[wid] = x;
    __syncthreads();
    if (tid < 32) {
        unsigned v = wsum[tid];
#pragma unroll
        for (int o = 1; o < 32; o <<= 1) {
            unsigned y = __shfl_up_sync(0xffffffffu, v, o);
            if (tid >= o) v += y;
        }
        wsum[tid] = v;
    }
    __syncthreads();
    unsigned incl = x + (wid ? wsum[wid - 1] : 0u);
    unsigned excl = incl - s;
    if (excl < TOPN && incl >= TOPN) {
        int cut; unsigned c;
        if (excl + h0 >= TOPN)                { cut = 4 * tid;     c = excl + h0; }
        else if (excl + h0 + h1 >= TOPN)      { cut = 4 * tid + 1; c = excl + h0 + h1; }
        else if (excl + h0 + h1 + h2 >= TOPN) { cut = 4 * tid + 2; c = excl + h0 + h1 + h2; }
        else                                  { cut = 4 * tid + 3; c = excl + h0 + h1 + h2 + h3; }
        s_cut = cut; s_tot = c;
    }
    __syncthreads();

    bool fast = (s_cut >= 0) && (s_tot <= 1024u) && (ccnt <= (unsigned)CAP);
    unsigned* sk32 = hist;
    unsigned long long* sk64 = (unsigned long long*)hist;
    unsigned long long key = ~0ull;

    if (fast) {
        unsigned ulimit = ((unsigned)s_cut + 1u) << 2;
        for (unsigned c = tid; c < cc; c += 1024) {
            unsigned k2 = cand[c];
            bool sel = (k2 >> 17) < ulimit;
            unsigned am = __activemask();
            unsigned bal = __ballot_sync(am, sel);
            if (bal) {
                int leader = __ffs(bal) - 1;
                unsigned base = 0;
                if (lane == leader) base = atomicAdd(&s_n, (unsigned)__popc(bal));
                base = __shfl_sync(am, base, leader);
                if (sel) sk32[base + __popc(bal & ((1u << lane) - 1u))] = k2;
            }
        }
        __syncthreads();
        unsigned n = s_n;
        unsigned v = (tid < (int)n) ? sk32[tid] : 0xFFFFFFFFu;
        __syncthreads();
#pragma unroll
        for (int kk = 2; kk <= 32; kk <<= 1) {
            for (int j = kk >> 1; j > 0; j >>= 1) {
                unsigned o = __shfl_xor_sync(0xffffffffu, v, j);
                bool keepmin = ((tid & kk) == 0) == ((tid & j) == 0);
                v = keepmin ? (v < o ? v : o) : (v > o ? v : o);
            }
        }
        for (int kk = 64; kk <= 1024; kk <<= 1) {
            for (int j = kk >> 1; j >= 32; j >>= 1) {
                sk32[tid] = v;
                __syncthreads();
                unsigned o = sk32[tid ^ j];
                __syncthreads();
                bool keepmin = ((tid & kk) == 0) == ((tid & j) == 0);
                v = keepmin ? (v < o ? v : o) : (v > o ? v : o);
            }
#pragma unroll
            for (int j = 16; j > 0; j >>= 1) {
                unsigned o = __shfl_xor_sync(0xffffffffu, v, j);
                bool keepmin = ((tid & kk) == 0) == ((tid & j) == 0);
                v = keepmin ? (v < o ? v : o) : (v > o ? v : o);
            }
        }
        key = (unsigned long long)v;
    } else {
        const unsigned* keys = g_keys + (size_t)b * An;
        unsigned long long pref = 0ull;
        int rankNeed = TOPN;
        __shared__ unsigned s_c;
        for (int bit = 48; bit >= 0; --bit) {
            if (tid == 0) s_c = 0u;
            __syncthreads();
            unsigned c = 0;
            for (int a = tid; a < An; a += 1024) {
                unsigned long long k = ((unsigned long long)keys[a] << 17) | (unsigned)a;
                if ((k >> (bit + 1)) == pref && !((k >> bit) & 1ull)) c++;
            }
#pragma unroll
            for (int o = 16; o; o >>= 1) c += __shfl_down_sync(0xffffffffu, c, o);
            if (lane == 0) atomicAdd(&s_c, c);
            __syncthreads();
            unsigned C0 = s_c;
            if (rankNeed <= (int)C0) pref <<= 1;
            else { pref = (pref << 1) | 1ull; rankNeed -= (int)C0; }
            __syncthreads();
        }
        for (int a = tid; a < An; a += 1024) {
            unsigned long long k = ((unsigned long long)keys[a] << 17) | (unsigned)a;
            if (k <= pref) {
                unsigned p = atomicAdd(&s_n, 1u);
                if (p < 1024u) sk64[p] = k;
            }
        }
        __syncthreads();
        unsigned n = s_n;
        if ((unsigned)tid >= n) sk64[tid] = ~0ull;
        __syncthreads();
        for (int kk = 2; kk <= 1024; kk <<= 1) {
            for (int j = kk >> 1; j > 0; j >>= 1) {
                int ixj = tid ^ j;
                if (ixj > tid) {
                    unsigned long long a0 = sk64[tid], a1 = sk64[ixj];
                    bool asc = (tid & kk) == 0;
                    if (asc ? (a0 > a1) : (a0 < a1)) { sk64[tid] = a1; sk64[ixj] = a0; }
                }
                __syncthreads();
            }
        }
        key = sk64[tid];
    }

    // gather + decode into registers
    unsigned n_real = s_n;
    float sc = 0.f;
    float4 mybox = make_float4(0.f, 0.f, 0.f, 0.f);
    float myarea = 1e9f;
    if (tid < TOPN && (unsigned)tid < n_real) {
        int a = (int)(key & 0x1FFFFull);
        unsigned u = (unsigned)(key >> 17);
        sc = (u >= 0x3F800000u) ? 0.f : __uint_as_float(0x3F800000u - u);
        sanchor[tid] = a;

        float4 rg = __ldg(reg + (size_t)b * An + a);
        float4 an = __ldg(anc + (size_t)b * An + a);
        float aw  = __fsub_rn(an.z, an.x), ah = __fsub_rn(an.w, an.y);
        float acx = __fadd_rn(an.x, __fmul_rn(0.5f, aw));
        float acy = __fadd_rn(an.y, __fmul_rn(0.5f, ah));
        float pw  = __fmul_rn(expf(rg.z), aw);
        float ph  = __fmul_rn(expf(rg.w), ah);
        float pcx = __fadd_rn(__fmul_rn(rg.x, aw), acx);
        float pcy = __fadd_rn(__fmul_rn(rg.y, ah), acy);
        float hw  = __fmul_rn(0.5f, pw), hh = __fmul_rn(0.5f, ph);
        mybox.x = truncf(__fsub_rn(pcx, hw));
        mybox.y = truncf(__fsub_rn(pcy, hh));
        mybox.z = truncf(__fadd_rn(pcx, hw));
        mybox.w = truncf(__fadd_rn(pcy, hh));
        myarea = fmaxf(__fmul_rn(__fsub_rn(mybox.z, mybox.x), __fsub_rn(mybox.w, mybox.y)), 1e-4f);
        sbox[tid] = mybox;
        sarea[tid] = myarea;
    } else {
        sanchor[tid] = -1;
        sbox[tid] = make_float4(1e9f, 1e9f, 1e9f, 1e9f);
        sarea[tid] = 1e9f;
    }
    bool valid = (tid < TOPN) && (sc > 0.05f);
    unsigned wm = __ballot_sync(0xffffffffu, valid);
    if (lane == 0) s_invalid[wid] = ~wm;
    if (tid == 0) g_ccnt[b] = 0u;             // reset for next graph replay
    __syncthreads();

    // ---- lazy chunked greedy NMS with transposed (lane-parallel) cross phase ----
    for (int c = 0; c < 32; ++c) {
        if (s_kcnt >= MAXOBJ) break;
        int cbase = c << 5;
        // cross: warp wid owns candidate (cbase+wid); lane t tests kept box t of chunk w
        {
            float4 bc = sbox[cbase + wid]; float ac = sarea[cbase + wid];
            bool crosshit = false;
            for (int w = 0; w < c; ++w) {
                unsigned kb = s_keptw[w];
                bool h = ((kb >> lane) & 1u) &&
                         iou_ge(sbox[(w << 5) + lane], sarea[(w << 5) + lane], bc, ac);
                crosshit = crosshit || __any_sync(0xffffffffu, h);
            }
            if (lane == 0) s_cross[wid] = crosshit ? 1u : 0u;
        }
        // matrix phase: warp wid computes intra-chunk row wid
        {
            float4 bw = sbox[cbase + wid]; float aw_ = sarea[cbase + wid];
            float4 bj = sbox[cbase + lane]; float aj = sarea[cbase + lane];
            bool hit2 = (lane > wid) && iou_ge(bw, aw_, bj, aj);
            unsigned row = __ballot_sync(0xffffffffu, hit2);
            if (lane == 0) hist[2048 + wid] = row;
        }
        __syncthreads();
        // closure (redundant per warp; consistent inputs)
        unsigned myrow = hist[2048 + lane];
        unsigned crossw = __ballot_sync(0xffffffffu, s_cross[lane] != 0u);
        unsigned sup32 = s_invalid[c] | crossw;
        unsigned kept32 = 0u;
#pragma unroll
        for (int t = 0; t < 32; ++t) {
            unsigned rowt = __shfl_sync(0xffffffffu, myrow, t);
            if (!((sup32 >> t) & 1u)) { kept32 |= (1u << t); sup32 |= rowt; }
        }
        if (tid == 0) { s_keptw[c] = kept32; s_kcnt += __popc(kept32); }
        __syncthreads();
    }

    // prefix popcount of kept words + kept-list build
    if (tid < 32) {
        unsigned kw = s_keptw[lane];
        int c = __popc(kw), xx = c;
#pragma unroll
        for (int o = 1; o < 32; o <<= 1) {
            int y = __shfl_up_sync(0xffffffffu, xx, o);
            if (lane >= o) xx += y;
        }
        s_base[lane] = xx - c;
    }
    __syncthreads();

    int myrank = -1;
    if (tid < TOPN) {
        unsigned kw = s_keptw[wid];
        if ((kw >> lane) & 1u) {
            int r = s_base[wid] + __popc(kw & ((1u << lane) - 1u));
            if (r < MAXOBJ) { myrank = r; s_list[r] = tid; }
        }
    }
    __syncthreads();

    // scores + boxes from registers
    if (myrank >= 0) {
        out[b * MAXOBJ + myrank] = sc;
        float* ob = out + 2 * Bn * MAXOBJ + (b * MAXOBJ + myrank) * 4;
        ob[0] = mybox.x; ob[1] = mybox.y; ob[2] = mybox.z; ob[3] = mybox.w;
    }

    // class argmax for kept rows only: 1 warp/row, lane f<20 loads float4 f
    int kmax = (s_kcnt < MAXOBJ) ? s_kcnt : MAXOBJ;
    const float4* clsb = cls4 + (size_t)b * An * 20;
    for (int r = wid; r < kmax; r += 32) {
        int a = sanchor[s_list[r]];
        float m = -1.f; int mi = 127;
        if (lane < 20) {
            float4 v = __ldg(clsb + (size_t)a * 20 + lane);
            ARGM(v, 4 * lane, m, mi);
        }
#pragma unroll
        for (int o = 1; o < 32; o <<= 1) {
            float om = __shfl_xor_sync(0xffffffffu, m, o);
            int   oi = __shfl_xor_sync(0xffffffffu, mi, o);
            if (om > m || (om == m && oi < mi)) { m = om; mi = oi; }
        }
        if (lane == 0) out[Bn * MAXOBJ + b * MAXOBJ + r] = (float)mi;
    }
}

extern "C" void kernel_launch(void* const* d_in, const int* in_sizes, int n_in,
                              void* d_out, int out_size) {
    const float*  cls = (const float*)d_in[0];
    const float4* reg = (const float4*)d_in[1];
    const float4* anc = (const float4*)d_in[2];
    float* out = (float*)d_out;

    k_score<<<(Bn * An / 2 * 8) / 256, 256>>>((const float4*)cls);
    k_post<<<Bn, 1024>>>((const float4*)cls, reg, anc, out);
}